// round 2
// baseline (speedup 1.0000x reference)
#include <cuda_runtime.h>
#include <math.h>

// ---------------- problem constants ----------------
#define BATCH 16
#define IMG   197
#define TXT   24
#define SEQ   222          // IMG + 1 + TXT
#define DIM   768
#define NH    12
#define HD    64
#define NL    6
#define VOC   50257
#define FF    3072
#define MROWS (BATCH*SEQ)  // 3552
#define QKVW  (3*DIM)      // 2304

// ---------------- device scratch (no allocations allowed) ----------------
__device__ float g_x   [MROWS*DIM];
__device__ float g_qkv [MROWS*QKVW];
__device__ float g_o   [MROWS*DIM];
__device__ float g_ff  [MROWS*FF];
__device__ float g_t   [MROWS*DIM];
__device__ float g_W   [DIM*QKVW];   // reshaped per-layer fused QKV weight [768 x 2304]
__device__ float g_b   [QKVW];

// ---------------- embedding: x = [img | sep | text_emb[tok]] ----------------
__global__ void embed_kernel(const float* __restrict__ img,
                             const int*   __restrict__ tok,
                             const float* __restrict__ temb,
                             const float* __restrict__ sep,
                             float* __restrict__ x)
{
    int row = blockIdx.x;            // b*SEQ + s
    int b = row / SEQ, s = row % SEQ;
    const float* src;
    if (s < IMG)        src = img + (size_t)(b*IMG + s)*DIM;
    else if (s == IMG)  src = sep;
    else                src = temb + (size_t)tok[b*TXT + (s-IMG-1)] * DIM;
    float* dst = x + (size_t)row*DIM;
    for (int i = threadIdx.x; i < DIM; i += blockDim.x) dst[i] = src[i];
}

// ---------------- per-layer weight reshape: (H,D,HD)x3 -> [D, 2304] ----------------
__global__ void reshape_w(const float* __restrict__ Wq, const float* __restrict__ Wk,
                          const float* __restrict__ Wv,
                          const float* __restrict__ bq, const float* __restrict__ bk,
                          const float* __restrict__ bv)
{
    int i = blockIdx.x*blockDim.x + threadIdx.x;
    const int per = DIM*DIM;
    if (i < 3*per) {
        int which = i / per;
        int rem   = i % per;
        int d = rem / DIM, c = rem % DIM;
        int h = c >> 6, e = c & 63;
        const float* W = (which == 0) ? Wq : (which == 1) ? Wk : Wv;
        g_W[(size_t)d*QKVW + which*DIM + c] = W[(size_t)h*DIM*HD + (size_t)d*HD + e];
    }
    if (i < QKVW) {
        int which = i / DIM, c = i % DIM;
        const float* bb = (which == 0) ? bq : (which == 1) ? bk : bv;
        g_b[i] = bb[c];
    }
}

// ---------------- generic SGEMM: C[M,N] = A[M,K] * B[K,N] + bias (opt relu) ------
// 128x128 block tile, BK=8, 256 threads, 8x8 per-thread microtile.
#define GBM 128
#define GBN 128
#define GBK 8
__global__ __launch_bounds__(256, 2)
void sgemm(const float* __restrict__ A, const float* __restrict__ Bm,
           const float* __restrict__ bias, float* __restrict__ C,
           int Mx, int Nx, int Kx, int relu)
{
    __shared__ __align__(16) float As[GBK][GBM];
    __shared__ __align__(16) float Bs[GBK][GBN];

    int tid = threadIdx.x;
    int m0 = blockIdx.x * GBM;     // x = M tiles so same-N blocks are adjacent -> B reuse in L2
    int n0 = blockIdx.y * GBN;
    int tx = tid & 15, ty = tid >> 4;

    float acc[8][8];
    #pragma unroll
    for (int i = 0; i < 8; i++)
        #pragma unroll
        for (int j = 0; j < 8; j++) acc[i][j] = 0.f;

    int arow = tid >> 1;            // 0..127
    int acol = (tid & 1) * 4;       // 0 or 4
    int brow = tid >> 5;            // 0..7
    int bcol = (tid & 31) * 4;      // 0..124

    for (int k0 = 0; k0 < Kx; k0 += GBK) {
        // A tile (float4; K is always a multiple of 8 & rows 16B-aligned here)
        int gm = m0 + arow;
        float4 av = make_float4(0.f,0.f,0.f,0.f);
        if (gm < Mx) av = *reinterpret_cast<const float4*>(A + (size_t)gm*Kx + k0 + acol);
        As[acol+0][arow] = av.x;
        As[acol+1][arow] = av.y;
        As[acol+2][arow] = av.z;
        As[acol+3][arow] = av.w;
        // B tile (scalar, N-guarded: ldb may be odd e.g. 50257)
        const float* Brow = Bm + (size_t)(k0 + brow)*Nx + n0;
        #pragma unroll
        for (int j = 0; j < 4; j++) {
            int n = bcol + j;
            Bs[brow][n] = (n0 + n < Nx) ? Brow[n] : 0.f;
        }
        __syncthreads();

        #pragma unroll
        for (int kk = 0; kk < GBK; kk++) {
            float a[8], bfr[8];
            #pragma unroll
            for (int i = 0; i < 8; i++) a[i]   = As[kk][ty*8 + i];
            #pragma unroll
            for (int j = 0; j < 8; j++) bfr[j] = Bs[kk][tx*8 + j];
            #pragma unroll
            for (int i = 0; i < 8; i++)
                #pragma unroll
                for (int j = 0; j < 8; j++)
                    acc[i][j] += a[i] * bfr[j];
        }
        __syncthreads();
    }

    #pragma unroll
    for (int i = 0; i < 8; i++) {
        int gm = m0 + ty*8 + i;
        if (gm >= Mx) continue;
        float* crow = C + (size_t)gm * Nx;
        #pragma unroll
        for (int j = 0; j < 8; j++) {
            int gn = n0 + tx*8 + j;
            if (gn >= Nx) continue;
            float v = acc[i][j] + (bias ? bias[gn] : 0.f);
            if (relu) v = fmaxf(v, 0.f);
            crow[gn] = v;
        }
    }
}

// ---------------- attention: per (b,h) block, K/V resident in smem -------------
#define KSTR 65   // padded row stride -> conflict-free strided dots
__global__ void attn_kernel(const float* __restrict__ qkv,
                            const int* __restrict__ tmask,
                            float* __restrict__ o)
{
    int b = blockIdx.x / NH, h = blockIdx.x % NH;
    extern __shared__ float sm[];
    float* ks = sm;                       // SEQ*KSTR
    float* vs = ks + SEQ*KSTR;            // SEQ*KSTR
    float* qs = vs + SEQ*KSTR;            // 8*64
    float* sc = qs + 8*64;                // 8*224
    unsigned char* valid = (unsigned char*)(sc + 8*224);

    int tid = threadIdx.x, lane = tid & 31, w = tid >> 5;
    const float* base = qkv + (size_t)b * SEQ * QKVW;

    for (int i = tid; i < SEQ*HD; i += 256) {
        int t = i >> 6, e = i & 63;
        ks[t*KSTR + e] = base[(size_t)t*QKVW +   DIM + h*64 + e];
        vs[t*KSTR + e] = base[(size_t)t*QKVW + 2*DIM + h*64 + e];
    }
    for (int t = tid; t < SEQ; t += 256)
        valid[t] = (t < SEQ - TXT) ? 1 : (tmask[b*TXT + t - (SEQ-TXT)] != 0);
    __syncthreads();

    float* myq  = qs + w*64;
    float* mysc = sc + w*224;
    for (int s = w; s < SEQ; s += 8) {
        myq[lane]      = base[(size_t)s*QKVW + h*64 + lane];
        myq[lane + 32] = base[(size_t)s*QKVW + h*64 + lane + 32];
        __syncwarp();

        float lmax = -INFINITY;
        for (int t = lane; t <= s; t += 32) {
            float d = -INFINITY;
            if (valid[t]) {
                d = 0.f;
                #pragma unroll
                for (int e = 0; e < 64; e++) d += myq[e] * ks[t*KSTR + e];
                d *= 0.125f;   // 1/sqrt(64)
            }
            mysc[t] = d;
            lmax = fmaxf(lmax, d);
        }
        #pragma unroll
        for (int off = 16; off; off >>= 1)
            lmax = fmaxf(lmax, __shfl_xor_sync(0xffffffffu, lmax, off));

        float lsum = 0.f;
        for (int t = lane; t <= s; t += 32) {
            float p = expf(mysc[t] - lmax);   // exp(-inf) = 0 for masked cols
            mysc[t] = p;
            lsum += p;
        }
        #pragma unroll
        for (int off = 16; off; off >>= 1)
            lsum += __shfl_xor_sync(0xffffffffu, lsum, off);
        float inv = 1.f / lsum;
        __syncwarp();

        float acc0 = 0.f, acc1 = 0.f;
        for (int t = 0; t <= s; t++) {
            float p = mysc[t];
            acc0 += p * vs[t*KSTR + lane];
            acc1 += p * vs[t*KSTR + lane + 32];
        }
        float* orow = o + (size_t)(b*SEQ + s)*DIM + h*64;
        orow[lane]      = acc0 * inv;
        orow[lane + 32] = acc1 * inv;
        __syncwarp();
    }
}

// ---------------- residual add + LayerNorm (row per block) ----------------
__global__ void add_ln_kernel(const float* __restrict__ x, const float* __restrict__ r,
                              const float* __restrict__ sc, const float* __restrict__ bi,
                              float* __restrict__ out)
{
    __shared__ float buf[DIM];
    __shared__ float red1[8], red2[8];
    int row = blockIdx.x, tid = threadIdx.x, lane = tid & 31, w = tid >> 5;
    const float* xr = x + (size_t)row*DIM;
    const float* rr = r + (size_t)row*DIM;

    float s = 0.f;
    for (int i = tid; i < DIM; i += 256) { float v = xr[i] + rr[i]; buf[i] = v; s += v; }
    #pragma unroll
    for (int off = 16; off; off >>= 1) s += __shfl_xor_sync(0xffffffffu, s, off);
    if (lane == 0) red1[w] = s;
    __syncthreads();
    float tot = 0.f;
    #pragma unroll
    for (int i = 0; i < 8; i++) tot += red1[i];
    float mu = tot * (1.f / DIM);

    float vsum = 0.f;
    for (int i = tid; i < DIM; i += 256) { float d = buf[i] - mu; vsum += d*d; }
    #pragma unroll
    for (int off = 16; off; off >>= 1) vsum += __shfl_xor_sync(0xffffffffu, vsum, off);
    if (lane == 0) red2[w] = vsum;
    __syncthreads();
    float vtot = 0.f;
    #pragma unroll
    for (int i = 0; i < 8; i++) vtot += red2[i];
    float inv = rsqrtf(vtot * (1.f / DIM) + 1e-5f);

    float* orow = out + (size_t)row*DIM;
    for (int i = tid; i < DIM; i += 256)
        orow[i] = (buf[i] - mu) * inv * sc[i] + bi[i];
}

// ---------------- in-place row softmax over VOC ----------------
__global__ void softmax_rows(float* __restrict__ out)
{
    int row = blockIdx.x, tid = threadIdx.x, lane = tid & 31, w = tid >> 5;
    float* p = out + (size_t)row * VOC;
    __shared__ float smm[8], sss[8];

    float m = -INFINITY, s = 0.f;
    for (int i = tid; i < VOC; i += 256) {
        float xv = p[i];
        if (xv > m) { s = s * expf(m - xv) + 1.f; m = xv; }
        else        { s += expf(xv - m); }
    }
    #pragma unroll
    for (int off = 16; off; off >>= 1) {
        float m2 = __shfl_xor_sync(0xffffffffu, m, off);
        float s2 = __shfl_xor_sync(0xffffffffu, s, off);
        float mn = fmaxf(m, m2);
        s = s * expf(m - mn) + s2 * expf(m2 - mn);
        m = mn;
    }
    if (lane == 0) { smm[w] = m; sss[w] = s; }
    __syncthreads();
    if (tid == 0) {
        float M = smm[0], Sv = sss[0];
        #pragma unroll
        for (int i = 1; i < 8; i++) {
            float m2 = smm[i], s2 = sss[i];
            float mn = fmaxf(M, m2);
            Sv = Sv * expf(M - mn) + s2 * expf(m2 - mn);
            M = mn;
        }
        smm[0] = M; sss[0] = 1.f / Sv;
    }
    __syncthreads();
    float M = smm[0], inv = sss[0];
    for (int i = tid; i < VOC; i += 256)
        p[i] = expf(p[i] - M) * inv;
}

// ---------------- host driver ----------------
static inline dim3 gemm_grid(int M, int N) {
    return dim3((M + GBM - 1)/GBM, (N + GBN - 1)/GBN);
}

extern "C" void kernel_launch(void* const* d_in, const int* in_sizes, int n_in,
                              void* d_out, int out_size)
{
    const float* img   = (const float*)d_in[0];
    const int*   tok   = (const int*)  d_in[1];
    const int*   tmask = (const int*)  d_in[2];   // bool transported as int32
    const float* temb  = (const float*)d_in[3];
    const float* sep   = (const float*)d_in[4];
    const float* Wq    = (const float*)d_in[5];
    const float* bq    = (const float*)d_in[6];
    const float* Wk    = (const float*)d_in[7];
    const float* bk    = (const float*)d_in[8];
    const float* Wv    = (const float*)d_in[9];
    const float* bv    = (const float*)d_in[10];
    const float* ln1s  = (const float*)d_in[11];
    const float* ln1b  = (const float*)d_in[12];
    const float* W1    = (const float*)d_in[13];
    const float* b1    = (const float*)d_in[14];
    const float* W2    = (const float*)d_in[15];
    const float* b2    = (const float*)d_in[16];
    const float* ln2s  = (const float*)d_in[17];
    const float* ln2b  = (const float*)d_in[18];
    const float* Wout  = (const float*)d_in[19];
    const float* bout  = (const float*)d_in[20];
    float* out = (float*)d_out;

    float *px, *pqkv, *po, *pff, *pt, *pW, *pb;
    cudaGetSymbolAddress((void**)&px,   g_x);
    cudaGetSymbolAddress((void**)&pqkv, g_qkv);
    cudaGetSymbolAddress((void**)&po,   g_o);
    cudaGetSymbolAddress((void**)&pff,  g_ff);
    cudaGetSymbolAddress((void**)&pt,   g_t);
    cudaGetSymbolAddress((void**)&pW,   g_W);
    cudaGetSymbolAddress((void**)&pb,   g_b);

    const int ATTN_SMEM = (SEQ*KSTR*2 + 8*64 + 8*224) * 4 + 256;
    cudaFuncSetAttribute(attn_kernel, cudaFuncAttributeMaxDynamicSharedMemorySize, ATTN_SMEM);

    embed_kernel<<<MROWS, 256>>>(img, tok, temb, sep, px);

    for (int l = 0; l < NL; l++) {
        const size_t woff = (size_t)l * NH * DIM * HD;
        reshape_w<<<(3*DIM*DIM + 255)/256, 256>>>(Wq + woff, Wk + woff, Wv + woff,
                                                  bq + (size_t)l*DIM,
                                                  bk + (size_t)l*DIM,
                                                  bv + (size_t)l*DIM);
        sgemm<<<gemm_grid(MROWS, QKVW), 256>>>(px, pW, pb, pqkv, MROWS, QKVW, DIM, 0);
        attn_kernel<<<BATCH*NH, 256, ATTN_SMEM>>>(pqkv, tmask, po);
        add_ln_kernel<<<MROWS, 256>>>(px, po, ln1s + (size_t)l*DIM, ln1b + (size_t)l*DIM, px);
        sgemm<<<gemm_grid(MROWS, FF), 256>>>(px, W1 + (size_t)l*DIM*FF, b1 + (size_t)l*FF,
                                             pff, MROWS, FF, DIM, 1);
        sgemm<<<gemm_grid(MROWS, DIM), 256>>>(pff, W2 + (size_t)l*FF*DIM, b2 + (size_t)l*DIM,
                                              pt, MROWS, DIM, FF, 0);
        add_ln_kernel<<<MROWS, 256>>>(px, pt, ln2s + (size_t)l*DIM, ln2b + (size_t)l*DIM, px);
    }

    sgemm<<<gemm_grid(MROWS, VOC), 256>>>(px, Wout, bout, out, MROWS, VOC, DIM, 0);
    softmax_rows<<<MROWS, 256>>>(out);
}

// round 4
// speedup vs baseline: 2.1616x; 2.1616x over previous
#include <cuda_runtime.h>
#include <cuda_bf16.h>
#include <math.h>
#include <stdint.h>

// ---------------- problem constants ----------------
#define BATCH 16
#define IMG   197
#define TXT   24
#define SEQ   222
#define DIM   768
#define NH    12
#define HD    64
#define NL    6
#define VOC   50257
#define FF    3072
#define MROWS (BATCH*SEQ)  // 3552
#define QKVW  (3*DIM)      // 2304
#define MPAD  3584         // 28 * 128
#define NPADV 50432        // 394 * 128
#define KMAX  3072

// ---------------- GEMM tiling (mma.sync path) ----------------
#define TKC   32                 // K per stage
#define ASTR  40                 // smem row stride in bf16 (80B = 20 banks -> conflict-free)
#define MATSZ (128*ASTR*2)       // 10240 B per matrix tile
#define STAGESZ (4*MATSZ)        // Ah,Al,Bh,Bl = 40960 B
#define DSMEM (2*STAGESZ)        // 81920 B

// ---------------- device scratch ----------------
__device__ float g_x   [MROWS*DIM];
__device__ float g_qkv [MROWS*QKVW];
__device__ float g_o   [MROWS*DIM];
__device__ float g_ff  [MROWS*FF];
__device__ float g_t   [MROWS*DIM];
__device__ float g_b   [QKVW];
__device__ __nv_bfloat16 g_ah [MPAD*KMAX];
__device__ __nv_bfloat16 g_al [MPAD*KMAX];
__device__ __nv_bfloat16 g_bth[(size_t)NPADV*DIM];
__device__ __nv_bfloat16 g_btl[(size_t)NPADV*DIM];
__device__ float g_logits[(size_t)MROWS*NPADV];

// ---------------- PTX helpers ----------------
__device__ __forceinline__ uint32_t s2u(const void* p) {
    uint32_t a;
    asm("{ .reg .u64 t; cvta.to.shared.u64 t, %1; cvt.u32.u64 %0, t; }" : "=r"(a) : "l"(p));
    return a;
}
#define CP16(dst, src)   asm volatile("cp.async.cg.shared.global [%0], [%1], 16;" :: "r"(dst), "l"(src))
#define CP_COMMIT()      asm volatile("cp.async.commit_group;" ::: "memory")
#define CP_WAIT(n)       asm volatile("cp.async.wait_group %0;" :: "n"(n) : "memory")

__device__ __forceinline__ void mma16816(float* c, const uint32_t* a, const uint32_t* b) {
    asm volatile(
        "mma.sync.aligned.m16n8k16.row.col.f32.bf16.bf16.f32 "
        "{%0,%1,%2,%3}, {%4,%5,%6,%7}, {%8,%9}, {%0,%1,%2,%3};"
        : "+f"(c[0]), "+f"(c[1]), "+f"(c[2]), "+f"(c[3])
        : "r"(a[0]), "r"(a[1]), "r"(a[2]), "r"(a[3]), "r"(b[0]), "r"(b[1]));
}

// ---------------- embedding ----------------
__global__ void embed_kernel(const float* __restrict__ img, const int* __restrict__ tok,
                             const float* __restrict__ temb, const float* __restrict__ sep,
                             float* __restrict__ x)
{
    int row = blockIdx.x;
    int b = row / SEQ, s = row % SEQ;
    const float* src;
    if (s < IMG)       src = img + (size_t)(b*IMG + s)*DIM;
    else if (s == IMG) src = sep;
    else               src = temb + (size_t)tok[b*TXT + (s-IMG-1)] * DIM;
    float* dst = x + (size_t)row*DIM;
    for (int i = threadIdx.x; i < DIM; i += blockDim.x) dst[i] = src[i];
}

// ---------------- activation split: fp32 [Ms,K] -> bf16 hi/lo [MPAD,K] ----------------
__global__ void a_convert(const float* __restrict__ src, int Ms, int K)
{
    size_t idx = (size_t)blockIdx.x*256 + threadIdx.x;
    if (idx >= (size_t)MPAD*K) return;
    int row = (int)(idx / K);
    float v = (row < Ms) ? src[idx] : 0.f;
    __nv_bfloat16 h = __float2bfloat16(v);
    g_ah[idx] = h;
    g_al[idx] = __float2bfloat16(v - __bfloat162float(h));
}

// ---------------- weight transpose+split: fp32 [K,N] -> bf16 hi/lo [Npad,K] ----------------
__global__ void wt_convert(const float* __restrict__ src, int K, int N)
{
    __shared__ float t[32][33];
    int n0 = blockIdx.x*32, k0 = blockIdx.y*32;
    int tx = threadIdx.x, ty = threadIdx.y;
    #pragma unroll
    for (int j = 0; j < 32; j += 8) {
        int n = n0 + tx;
        t[ty+j][tx] = (n < N) ? src[(size_t)(k0+ty+j)*N + n] : 0.f;
    }
    __syncthreads();
    #pragma unroll
    for (int j = 0; j < 32; j += 8) {
        int n = n0 + ty + j, k = k0 + tx;
        float v = t[tx][ty+j];
        __nv_bfloat16 h = __float2bfloat16(v);
        size_t o = (size_t)n*K + k;
        g_bth[o] = h;
        g_btl[o] = __float2bfloat16(v - __bfloat162float(h));
    }
}

// ---------------- QKV weight gather+split: (H,D,HD)x3 -> bf16 hi/lo [2304,768] -------------
__global__ void qkvw_convert(const float* __restrict__ Wq, const float* __restrict__ Wk,
                             const float* __restrict__ Wv,
                             const float* __restrict__ bq, const float* __restrict__ bk,
                             const float* __restrict__ bv)
{
    int idx = blockIdx.x*256 + threadIdx.x;
    if (idx < QKVW*DIM) {
        int c = idx / DIM, d = idx % DIM;
        int which = c / DIM, w2 = c % DIM;
        int h = w2 >> 6, e = w2 & 63;
        const float* W = (which == 0) ? Wq : (which == 1) ? Wk : Wv;
        float v = W[(size_t)h*DIM*HD + (size_t)d*HD + e];
        __nv_bfloat16 hh = __float2bfloat16(v);
        g_bth[idx] = hh;
        g_btl[idx] = __float2bfloat16(v - __bfloat162float(hh));
    }
    if (idx < QKVW) {
        int which = idx / DIM, cc = idx % DIM;
        const float* bb = (which == 0) ? bq : (which == 1) ? bk : bv;
        g_b[idx] = bb[cc];
    }
}

// ---------------- mma.sync bf16 3-pass GEMM: C[Mreal,ldc] = A*B^T + bias ----------------
// CTA tile 128x128, 8 warps of 64x32, Kc=32 double-buffered via cp.async.
__global__ __launch_bounds__(256, 1)
void gemm_mma(const __nv_bfloat16* __restrict__ Ah, const __nv_bfloat16* __restrict__ Al,
              const __nv_bfloat16* __restrict__ Bh, const __nv_bfloat16* __restrict__ Bl,
              const float* __restrict__ bias, float* __restrict__ C,
              int K, int ldc, int Nreal, int Mreal, int relu)
{
    extern __shared__ char dsm[];
    const int tid = threadIdx.x;
    const int wid = tid >> 5, lane = tid & 31;
    const int m0 = blockIdx.x * 128, n0 = blockIdx.y * 128;
    const int wm = wid >> 2, wn = wid & 3;     // warp tile: rows wm*64, cols wn*32
    const int g = lane >> 2, t = lane & 3;
    const int nk = K / TKC;
    const uint32_t sb = s2u(dsm);

    float acc[4][4][4];
    #pragma unroll
    for (int mi = 0; mi < 4; mi++)
        #pragma unroll
        for (int ni = 0; ni < 4; ni++)
            #pragma unroll
            for (int r = 0; r < 4; r++) acc[mi][ni][r] = 0.f;

    // loader: stage p <- K-chunk kc. 2048 x 16B chunks, 256 thr -> 8 each.
    #define LOAD_ST(p, kc) do {                                                     \
        int k0_ = (kc) * TKC;                                                       \
        for (int c_ = tid; c_ < 2048; c_ += 256) {                                  \
            int mat_ = c_ >> 9, mr_ = c_ & 511;                                     \
            int row_ = mr_ >> 2, c16_ = mr_ & 3;                                    \
            const __nv_bfloat16* sp_ =                                              \
                ((mat_ == 0) ? Ah : (mat_ == 1) ? Al : (mat_ == 2) ? Bh : Bl)       \
                + (size_t)(((mat_ < 2) ? m0 : n0) + row_) * K + k0_ + c16_*8;       \
            uint32_t dst_ = sb + (p)*STAGESZ + mat_*MATSZ + row_*80 + c16_*16;      \
            CP16(dst_, sp_);                                                        \
        }                                                                           \
    } while (0)

    LOAD_ST(0, 0);
    CP_COMMIT();

    for (int kc = 0; kc < nk; kc++) {
        int p = kc & 1;
        if (kc + 1 < nk) {
            LOAD_ST(p ^ 1, kc + 1);
            CP_COMMIT();
            CP_WAIT(1);
        } else {
            CP_WAIT(0);
        }
        __syncthreads();

        const __nv_bfloat16* sAh = (const __nv_bfloat16*)(dsm + p*STAGESZ);
        const __nv_bfloat16* sAl = (const __nv_bfloat16*)(dsm + p*STAGESZ + MATSZ);
        const __nv_bfloat16* sBh = (const __nv_bfloat16*)(dsm + p*STAGESZ + 2*MATSZ);
        const __nv_bfloat16* sBl = (const __nv_bfloat16*)(dsm + p*STAGESZ + 3*MATSZ);

        #pragma unroll
        for (int ks = 0; ks < 2; ks++) {
            int kb = ks * 16;
            uint32_t ah[4][4], al[4][4], bb[4][2];
            #pragma unroll
            for (int mi = 0; mi < 4; mi++) {
                int r = wm*64 + mi*16 + g;
                ah[mi][0] = *(const uint32_t*)&sAh[r*ASTR     + kb + t*2];
                ah[mi][1] = *(const uint32_t*)&sAh[(r+8)*ASTR + kb + t*2];
                ah[mi][2] = *(const uint32_t*)&sAh[r*ASTR     + kb + t*2 + 8];
                ah[mi][3] = *(const uint32_t*)&sAh[(r+8)*ASTR + kb + t*2 + 8];
                al[mi][0] = *(const uint32_t*)&sAl[r*ASTR     + kb + t*2];
                al[mi][1] = *(const uint32_t*)&sAl[(r+8)*ASTR + kb + t*2];
                al[mi][2] = *(const uint32_t*)&sAl[r*ASTR     + kb + t*2 + 8];
                al[mi][3] = *(const uint32_t*)&sAl[(r+8)*ASTR + kb + t*2 + 8];
            }
            #pragma unroll
            for (int ni = 0; ni < 4; ni++) {
                int rn = wn*32 + ni*8 + g;
                bb[ni][0] = *(const uint32_t*)&sBh[rn*ASTR + kb + t*2];
                bb[ni][1] = *(const uint32_t*)&sBh[rn*ASTR + kb + t*2 + 8];
            }
            #pragma unroll
            for (int mi = 0; mi < 4; mi++)
                #pragma unroll
                for (int ni = 0; ni < 4; ni++)
                    mma16816(acc[mi][ni], ah[mi], bb[ni]);
            #pragma unroll
            for (int mi = 0; mi < 4; mi++)
                #pragma unroll
                for (int ni = 0; ni < 4; ni++)
                    mma16816(acc[mi][ni], al[mi], bb[ni]);
            #pragma unroll
            for (int ni = 0; ni < 4; ni++) {
                int rn = wn*32 + ni*8 + g;
                bb[ni][0] = *(const uint32_t*)&sBl[rn*ASTR + kb + t*2];
                bb[ni][1] = *(const uint32_t*)&sBl[rn*ASTR + kb + t*2 + 8];
            }
            #pragma unroll
            for (int mi = 0; mi < 4; mi++)
                #pragma unroll
                for (int ni = 0; ni < 4; ni++)
                    mma16816(acc[mi][ni], ah[mi], bb[ni]);
        }
        __syncthreads();
    }

    // epilogue
    #pragma unroll
    for (int mi = 0; mi < 4; mi++) {
        int gm0 = m0 + wm*64 + mi*16 + g;
        #pragma unroll
        for (int ni = 0; ni < 4; ni++) {
            int gn = n0 + wn*32 + ni*8 + t*2;
            float bx = (gn     < Nreal) ? bias[gn]     : 0.f;
            float by = (gn + 1 < Nreal) ? bias[gn + 1] : 0.f;
            float c0 = acc[mi][ni][0] + bx, c1 = acc[mi][ni][1] + by;
            float c2 = acc[mi][ni][2] + bx, c3 = acc[mi][ni][3] + by;
            if (relu) {
                c0 = fmaxf(c0, 0.f); c1 = fmaxf(c1, 0.f);
                c2 = fmaxf(c2, 0.f); c3 = fmaxf(c3, 0.f);
            }
            if (gm0 < Mreal)
                *reinterpret_cast<float2*>(C + (size_t)gm0*ldc + gn) = make_float2(c0, c1);
            if (gm0 + 8 < Mreal)
                *reinterpret_cast<float2*>(C + (size_t)(gm0+8)*ldc + gn) = make_float2(c2, c3);
        }
    }
}

// ---------------- attention: 4-way q split per (b,h) ----------------
#define KSTR 65
__global__ void attn_kernel(const float* __restrict__ qkv,
                            const int* __restrict__ tmask,
                            float* __restrict__ o)
{
    int bh = blockIdx.x >> 2, z = blockIdx.x & 3;
    int b = bh / NH, h = bh % NH;
    extern __shared__ float sm[];
    float* ks = sm;
    float* vs = ks + SEQ*KSTR;
    float* qs = vs + SEQ*KSTR;
    float* sc = qs + 8*64;
    unsigned char* valid = (unsigned char*)(sc + 8*224);

    int tid = threadIdx.x, lane = tid & 31, w = tid >> 5;
    const float* base = qkv + (size_t)b * SEQ * QKVW;

    for (int i = tid; i < SEQ*HD; i += 256) {
        int t = i >> 6, e = i & 63;
        ks[t*KSTR + e] = base[(size_t)t*QKVW +   DIM + h*64 + e];
        vs[t*KSTR + e] = base[(size_t)t*QKVW + 2*DIM + h*64 + e];
    }
    for (int t = tid; t < SEQ; t += 256)
        valid[t] = (t < SEQ - TXT) ? 1 : (tmask[b*TXT + t - (SEQ-TXT)] != 0);
    __syncthreads();

    float* myq  = qs + w*64;
    float* mysc = sc + w*224;
    for (int s = (w << 2) + z; s < SEQ; s += 32) {
        myq[lane]      = base[(size_t)s*QKVW + h*64 + lane];
        myq[lane + 32] = base[(size_t)s*QKVW + h*64 + lane + 32];
        __syncwarp();

        float lmax = -INFINITY;
        for (int t = lane; t <= s; t += 32) {
            float d = -INFINITY;
            if (valid[t]) {
                d = 0.f;
                #pragma unroll
                for (int e = 0; e < 64; e++) d += myq[e] * ks[t*KSTR + e];
                d *= 0.125f;
            }
            mysc[t] = d;
            lmax = fmaxf(lmax, d);
        }
        #pragma unroll
        for (int off = 16; off; off >>= 1)
            lmax = fmaxf(lmax, __shfl_xor_sync(0xffffffffu, lmax, off));

        float lsum = 0.f;
        for (int t = lane; t <= s; t += 32) {
            float p = expf(mysc[t] - lmax);
            mysc[t] = p;
            lsum += p;
        }
        #pragma unroll
        for (int off = 16; off; off >>= 1)
            lsum += __shfl_xor_sync(0xffffffffu, lsum, off);
        float inv = 1.f / lsum;
        __syncwarp();

        float acc0 = 0.f, acc1 = 0.f;
        for (int t = 0; t <= s; t++) {
            float p = mysc[t];
            acc0 += p * vs[t*KSTR + lane];
            acc1 += p * vs[t*KSTR + lane + 32];
        }
        float* orow = o + (size_t)(b*SEQ + s)*DIM + h*64;
        orow[lane]      = acc0 * inv;
        orow[lane + 32] = acc1 * inv;
        __syncwarp();
    }
}

// ---------------- residual add + LayerNorm ----------------
__global__ void add_ln_kernel(const float* __restrict__ x, const float* __restrict__ r,
                              const float* __restrict__ sc, const float* __restrict__ bi,
                              float* __restrict__ out)
{
    __shared__ float buf[DIM];
    __shared__ float red1[8], red2[8];
    int row = blockIdx.x, tid = threadIdx.x, lane = tid & 31, w = tid >> 5;
    const float* xr = x + (size_t)row*DIM;
    const float* rr = r + (size_t)row*DIM;

    float s = 0.f;
    for (int i = tid; i < DIM; i += 256) { float v = xr[i] + rr[i]; buf[i] = v; s += v; }
    #pragma unroll
    for (int off = 16; off; off >>= 1) s += __shfl_xor_sync(0xffffffffu, s, off);
    if (lane == 0) red1[w] = s;
    __syncthreads();
    float tot = 0.f;
    #pragma unroll
    for (int i = 0; i < 8; i++) tot += red1[i];
    float mu = tot * (1.f / DIM);

    float vsum = 0.f;
    for (int i = tid; i < DIM; i += 256) { float d = buf[i] - mu; vsum += d*d; }
    #pragma unroll
    for (int off = 16; off; off >>= 1) vsum += __shfl_xor_sync(0xffffffffu, vsum, off);
    if (lane == 0) red2[w] = vsum;
    __syncthreads();
    float vtot = 0.f;
    #pragma unroll
    for (int i = 0; i < 8; i++) vtot += red2[i];
    float inv = rsqrtf(vtot * (1.f / DIM) + 1e-5f);

    float* orow = out + (size_t)row*DIM;
    for (int i = tid; i < DIM; i += 256)
        orow[i] = (buf[i] - mu) * inv * sc[i] + bi[i];
}

// ---------------- softmax: padded logits -> d_out ----------------
__global__ void softmax_rows(const float* __restrict__ in, float* __restrict__ out)
{
    int row = blockIdx.x, tid = threadIdx.x, lane = tid & 31, w = tid >> 5;
    const float* p = in + (size_t)row * NPADV;
    float* q = out + (size_t)row * VOC;
    __shared__ float smm[8], sss[8];

    float m = -INFINITY, s = 0.f;
    for (int i = tid; i < VOC; i += 256) {
        float xv = p[i];
        if (xv > m) { s = s * expf(m - xv) + 1.f; m = xv; }
        else        { s += expf(xv - m); }
    }
    #pragma unroll
    for (int off = 16; off; off >>= 1) {
        float m2 = __shfl_xor_sync(0xffffffffu, m, off);
        float s2 = __shfl_xor_sync(0xffffffffu, s, off);
        float mn = fmaxf(m, m2);
        s = s * expf(m - mn) + s2 * expf(m2 - mn);
        m = mn;
    }
    if (lane == 0) { smm[w] = m; sss[w] = s; }
    __syncthreads();
    if (tid == 0) {
        float M = smm[0], Sv = sss[0];
        #pragma unroll
        for (int i = 1; i < 8; i++) {
            float m2 = smm[i], s2 = sss[i];
            float mn = fmaxf(M, m2);
            Sv = Sv * expf(M - mn) + s2 * expf(m2 - mn);
            M = mn;
        }
        smm[0] = M; sss[0] = 1.f / Sv;
    }
    __syncthreads();
    float M = smm[0], inv = sss[0];
    for (int i = tid; i < VOC; i += 256)
        q[i] = expf(p[i] - M) * inv;
}

// ---------------- host driver ----------------
extern "C" void kernel_launch(void* const* d_in, const int* in_sizes, int n_in,
                              void* d_out, int out_size)
{
    const float* img   = (const float*)d_in[0];
    const int*   tok   = (const int*)  d_in[1];
    const int*   tmask = (const int*)  d_in[2];
    const float* temb  = (const float*)d_in[3];
    const float* sep   = (const float*)d_in[4];
    const float* Wq    = (const float*)d_in[5];
    const float* bq    = (const float*)d_in[6];
    const float* Wk    = (const float*)d_in[7];
    const float* bk    = (const float*)d_in[8];
    const float* Wv    = (const float*)d_in[9];
    const float* bv    = (const float*)d_in[10];
    const float* ln1s  = (const float*)d_in[11];
    const float* ln1b  = (const float*)d_in[12];
    const float* W1    = (const float*)d_in[13];
    const float* b1    = (const float*)d_in[14];
    const float* W2    = (const float*)d_in[15];
    const float* b2    = (const float*)d_in[16];
    const float* ln2s  = (const float*)d_in[17];
    const float* ln2b  = (const float*)d_in[18];
    const float* Wout  = (const float*)d_in[19];
    const float* bout  = (const float*)d_in[20];
    float* out = (float*)d_out;

    float *px, *pqkv, *po, *pff, *pt, *pb, *plog;
    __nv_bfloat16 *pah, *pal, *pbh, *pbl;
    cudaGetSymbolAddress((void**)&px,   g_x);
    cudaGetSymbolAddress((void**)&pqkv, g_qkv);
    cudaGetSymbolAddress((void**)&po,   g_o);
    cudaGetSymbolAddress((void**)&pff,  g_ff);
    cudaGetSymbolAddress((void**)&pt,   g_t);
    cudaGetSymbolAddress((void**)&pb,   g_b);
    cudaGetSymbolAddress((void**)&plog, g_logits);
    cudaGetSymbolAddress((void**)&pah,  g_ah);
    cudaGetSymbolAddress((void**)&pal,  g_al);
    cudaGetSymbolAddress((void**)&pbh,  g_bth);
    cudaGetSymbolAddress((void**)&pbl,  g_btl);

    const int ATTN_SMEM = (SEQ*KSTR*2 + 8*64 + 8*224) * 4 + 256;
    cudaFuncSetAttribute(attn_kernel, cudaFuncAttributeMaxDynamicSharedMemorySize, ATTN_SMEM);
    cudaFuncSetAttribute(gemm_mma, cudaFuncAttributeMaxDynamicSharedMemorySize, DSMEM);

    embed_kernel<<<MROWS, 256>>>(img, tok, temb, sep, px);

    #define ACONV(src, K)  a_convert<<<(int)(((size_t)MPAD*(K) + 255)/256), 256>>>(src, MROWS, K)
    #define GEMM(bias, C, K, ldc, Nreal, Npad, relu) \
        gemm_mma<<<dim3(MPAD/128, (Npad)/128), 256, DSMEM>>>(pah, pal, pbh, pbl, bias, C, K, ldc, Nreal, MROWS, relu)

    for (int l = 0; l < NL; l++) {
        const size_t woff = (size_t)l * NH * DIM * HD;
        // QKV
        qkvw_convert<<<(QKVW*DIM + 255)/256, 256>>>(Wq + woff, Wk + woff, Wv + woff,
                                                    bq + (size_t)l*DIM, bk + (size_t)l*DIM,
                                                    bv + (size_t)l*DIM);
        ACONV(px, DIM);
        GEMM(pb, pqkv, DIM, QKVW, QKVW, QKVW, 0);
        attn_kernel<<<BATCH*NH*4, 256, ATTN_SMEM>>>(pqkv, tmask, po);
        add_ln_kernel<<<MROWS, 256>>>(px, po, ln1s + (size_t)l*DIM, ln1b + (size_t)l*DIM, px);
        // FFN1
        ACONV(px, DIM);
        wt_convert<<<dim3(FF/32, DIM/32), dim3(32, 8)>>>(W1 + (size_t)l*DIM*FF, DIM, FF);
        GEMM(b1 + (size_t)l*FF, pff, DIM, FF, FF, FF, 1);
        // FFN2
        ACONV(pff, FF);
        wt_convert<<<dim3(DIM/32, FF/32), dim3(32, 8)>>>(W2 + (size_t)l*FF*DIM, FF, DIM);
        GEMM(b2 + (size_t)l*DIM, pt, FF, DIM, DIM, DIM, 0);
        add_ln_kernel<<<MROWS, 256>>>(px, pt, ln2s + (size_t)l*DIM, ln2b + (size_t)l*DIM, px);
    }

    // vocab projection (padded logits) + softmax into d_out
    ACONV(px, DIM);
    wt_convert<<<dim3(NPADV/32, DIM/32), dim3(32, 8)>>>(Wout, DIM, VOC);
    GEMM(bout, plog, DIM, NPADV, VOC, NPADV, 0);
    softmax_rows<<<MROWS, 256>>>(plog, out);
}

// round 5
// speedup vs baseline: 2.5822x; 1.1946x over previous
#include <cuda_runtime.h>
#include <cuda_bf16.h>
#include <math.h>
#include <stdint.h>

// ---------------- problem constants ----------------
#define BATCH 16
#define IMG   197
#define TXT   24
#define SEQ   222
#define DIM   768
#define NH    12
#define HD    64
#define NL    6
#define VOC   50257
#define FF    3072
#define MROWS (BATCH*SEQ)  // 3552
#define QKVW  (3*DIM)      // 2304
#define MPAD  3584         // 28 * 128
#define NPADV 50432        // 394 * 128
#define KMAX  3072

// ---------------- GEMM tiling (mma.sync + ldmatrix path) ----------------
#define TKC   32                 // K per stage
#define ASTR  40                 // smem row stride in bf16 (80B -> conflict-free LDS/LDSM)
#define MATSZ (128*ASTR*2)       // 10240 B per matrix tile
#define STAGESZ (4*MATSZ)        // Ah,Al,Bh,Bl = 40960 B
#define DSMEM (2*STAGESZ)        // 81920 B  (x2 CTAs = 160KB < 228KB)
#define MIOFF (16*ASTR*2)        // 1280 B: 16 rows

// ---------------- device scratch ----------------
__device__ float g_x   [MROWS*DIM];
__device__ float g_qkv [MROWS*QKVW];
__device__ float g_o   [MROWS*DIM];
__device__ float g_ff  [MROWS*FF];
__device__ float g_t   [MROWS*DIM];
__device__ float g_b   [QKVW];
__device__ __nv_bfloat16 g_ah [MPAD*KMAX];
__device__ __nv_bfloat16 g_al [MPAD*KMAX];
__device__ __nv_bfloat16 g_bth[(size_t)NPADV*DIM];
__device__ __nv_bfloat16 g_btl[(size_t)NPADV*DIM];
__device__ float g_logits[(size_t)MROWS*NPADV];

// ---------------- PTX helpers ----------------
__device__ __forceinline__ uint32_t s2u(const void* p) {
    uint32_t a;
    asm("{ .reg .u64 t; cvta.to.shared.u64 t, %1; cvt.u32.u64 %0, t; }" : "=r"(a) : "l"(p));
    return a;
}
#define CP16(dst, src)   asm volatile("cp.async.cg.shared.global [%0], [%1], 16;" :: "r"(dst), "l"(src))
#define CP_COMMIT()      asm volatile("cp.async.commit_group;" ::: "memory")
#define CP_WAIT(n)       asm volatile("cp.async.wait_group %0;" :: "n"(n) : "memory")

__device__ __forceinline__ void mma16816(float* c, const uint32_t* a, const uint32_t* b) {
    asm volatile(
        "mma.sync.aligned.m16n8k16.row.col.f32.bf16.bf16.f32 "
        "{%0,%1,%2,%3}, {%4,%5,%6,%7}, {%8,%9}, {%0,%1,%2,%3};"
        : "+f"(c[0]), "+f"(c[1]), "+f"(c[2]), "+f"(c[3])
        : "r"(a[0]), "r"(a[1]), "r"(a[2]), "r"(a[3]), "r"(b[0]), "r"(b[1]));
}
__device__ __forceinline__ void ldsm4(uint32_t* r, uint32_t addr) {
    asm volatile("ldmatrix.sync.aligned.m8n8.x4.shared.b16 {%0,%1,%2,%3}, [%4];"
                 : "=r"(r[0]), "=r"(r[1]), "=r"(r[2]), "=r"(r[3]) : "r"(addr));
}

// ---------------- embedding ----------------
__global__ void embed_kernel(const float* __restrict__ img, const int* __restrict__ tok,
                             const float* __restrict__ temb, const float* __restrict__ sep,
                             float* __restrict__ x)
{
    int row = blockIdx.x;
    int b = row / SEQ, s = row % SEQ;
    const float* src;
    if (s < IMG)       src = img + (size_t)(b*IMG + s)*DIM;
    else if (s == IMG) src = sep;
    else               src = temb + (size_t)tok[b*TXT + (s-IMG-1)] * DIM;
    float* dst = x + (size_t)row*DIM;
    for (int i = threadIdx.x; i < DIM; i += blockDim.x) dst[i] = src[i];
}

// ---------------- activation split: fp32 [Ms,K] -> bf16 hi/lo [MPAD,K] ----------------
__global__ void a_convert(const float* __restrict__ src, int Ms, int K)
{
    size_t idx = (size_t)blockIdx.x*256 + threadIdx.x;
    if (idx >= (size_t)MPAD*K) return;
    int row = (int)(idx / K);
    float v = (row < Ms) ? src[idx] : 0.f;
    __nv_bfloat16 h = __float2bfloat16(v);
    g_ah[idx] = h;
    g_al[idx] = __float2bfloat16(v - __bfloat162float(h));
}

// ---------------- weight transpose+split: fp32 [K,N] -> bf16 hi/lo [Npad,K] ----------------
__global__ void wt_convert(const float* __restrict__ src, int K, int N)
{
    __shared__ float t[32][33];
    int n0 = blockIdx.x*32, k0 = blockIdx.y*32;
    int tx = threadIdx.x, ty = threadIdx.y;
    #pragma unroll
    for (int j = 0; j < 32; j += 8) {
        int n = n0 + tx;
        t[ty+j][tx] = (n < N) ? src[(size_t)(k0+ty+j)*N + n] : 0.f;
    }
    __syncthreads();
    #pragma unroll
    for (int j = 0; j < 32; j += 8) {
        int n = n0 + ty + j, k = k0 + tx;
        float v = t[tx][ty+j];
        __nv_bfloat16 h = __float2bfloat16(v);
        size_t o = (size_t)n*K + k;
        g_bth[o] = h;
        g_btl[o] = __float2bfloat16(v - __bfloat162float(h));
    }
}

// ---------------- QKV weight gather+split: (H,D,HD)x3 -> bf16 hi/lo [2304,768] -------------
__global__ void qkvw_convert(const float* __restrict__ Wq, const float* __restrict__ Wk,
                             const float* __restrict__ Wv,
                             const float* __restrict__ bq, const float* __restrict__ bk,
                             const float* __restrict__ bv)
{
    int idx = blockIdx.x*256 + threadIdx.x;
    if (idx < QKVW*DIM) {
        int c = idx / DIM, d = idx % DIM;
        int which = c / DIM, w2 = c % DIM;
        int h = w2 >> 6, e = w2 & 63;
        const float* W = (which == 0) ? Wq : (which == 1) ? Wk : Wv;
        float v = W[(size_t)h*DIM*HD + (size_t)d*HD + e];
        __nv_bfloat16 hh = __float2bfloat16(v);
        g_bth[idx] = hh;
        g_btl[idx] = __float2bfloat16(v - __bfloat162float(hh));
    }
    if (idx < QKVW) {
        int which = idx / DIM, cc = idx % DIM;
        const float* bb = (which == 0) ? bq : (which == 1) ? bk : bv;
        g_b[idx] = bb[cc];
    }
}

// ---------------- mma.sync bf16 3-pass GEMM: C[Mreal,ldc] = A*B^T + bias ----------------
// CTA tile 128x128, 8 warps of 64x32, Kc=32 double-buffered cp.async, ldmatrix frags,
// 2 CTAs/SM via register reuse (Ah frag regs reused for Al).
__global__ __launch_bounds__(256, 2)
void gemm_mma(const __nv_bfloat16* __restrict__ Ah, const __nv_bfloat16* __restrict__ Al,
              const __nv_bfloat16* __restrict__ Bh, const __nv_bfloat16* __restrict__ Bl,
              const float* __restrict__ bias, float* __restrict__ C,
              int K, int ldc, int Nreal, int Mreal, int relu)
{
    extern __shared__ char dsm[];
    const int tid = threadIdx.x;
    const int wid = tid >> 5, lane = tid & 31;
    const int m0 = blockIdx.x * 128, n0 = blockIdx.y * 128;
    const int wm = wid >> 2, wn = wid & 3;     // warp tile: rows wm*64, cols wn*32
    const int g = lane >> 2, t = lane & 3;
    const int nk = K / TKC;
    const uint32_t sb = s2u(dsm);

    // ldmatrix lane-address components
    const int lm = lane >> 3, lj = lane & 7;   // matrix idx, row-in-matrix
    //  A frags: matrices [m0-7,k0-7],[m8-15,k0-7],[m0-7,k8-15],[m8-15,k8-15]
    const uint32_t aLane = ((uint32_t)((wm*64 + (lm & 1)*8 + lj) * ASTR + ((lm >> 1) * 8))) * 2;
    //  B frags (pair of n8 tiles): [n0-7,k0-7],[n0-7,k8-15],[n8-15,k0-7],[n8-15,k8-15]
    const uint32_t bLane = ((uint32_t)((wn*32 + (lm >> 1)*8 + lj) * ASTR + ((lm & 1) * 8))) * 2;

    float acc[4][4][4];
    #pragma unroll
    for (int mi = 0; mi < 4; mi++)
        #pragma unroll
        for (int ni = 0; ni < 4; ni++)
            #pragma unroll
            for (int r = 0; r < 4; r++) acc[mi][ni][r] = 0.f;

    #define LOAD_ST(p, kc) do {                                                     \
        int k0_ = (kc) * TKC;                                                       \
        for (int c_ = tid; c_ < 2048; c_ += 256) {                                  \
            int mat_ = c_ >> 9, mr_ = c_ & 511;                                     \
            int row_ = mr_ >> 2, c16_ = mr_ & 3;                                    \
            const __nv_bfloat16* sp_ =                                              \
                ((mat_ == 0) ? Ah : (mat_ == 1) ? Al : (mat_ == 2) ? Bh : Bl)       \
                + (size_t)(((mat_ < 2) ? m0 : n0) + row_) * K + k0_ + c16_*8;       \
            uint32_t dst_ = sb + (p)*STAGESZ + mat_*MATSZ + row_*80 + c16_*16;      \
            CP16(dst_, sp_);                                                        \
        }                                                                           \
    } while (0)

    LOAD_ST(0, 0);
    CP_COMMIT();

    for (int kc = 0; kc < nk; kc++) {
        int p = kc & 1;
        if (kc + 1 < nk) {
            LOAD_ST(p ^ 1, kc + 1);
            CP_COMMIT();
            CP_WAIT(1);
        } else {
            CP_WAIT(0);
        }
        __syncthreads();

        const uint32_t stg = sb + p*STAGESZ;
        const uint32_t aB = stg + aLane;              // Ah base (Al = +MATSZ)
        const uint32_t bB = stg + 2*MATSZ + bLane;    // Bh base (Bl = +MATSZ)

        #pragma unroll
        for (int ks = 0; ks < 2; ks++) {
            const uint32_t kof = ks * 32;             // kb*2 bytes
            uint32_t bhf[8], blf[8], af[16];
            ldsm4(bhf,     bB + kof);
            ldsm4(bhf + 4, bB + MIOFF + kof);
            ldsm4(blf,     bB + MATSZ + kof);
            ldsm4(blf + 4, bB + MATSZ + MIOFF + kof);
            #pragma unroll
            for (int mi = 0; mi < 4; mi++) ldsm4(af + mi*4, aB + mi*MIOFF + kof);
            #pragma unroll
            for (int mi = 0; mi < 4; mi++)
                #pragma unroll
                for (int ni = 0; ni < 4; ni++)
                    mma16816(acc[mi][ni], af + mi*4, bhf + ni*2);
            #pragma unroll
            for (int mi = 0; mi < 4; mi++)
                #pragma unroll
                for (int ni = 0; ni < 4; ni++)
                    mma16816(acc[mi][ni], af + mi*4, blf + ni*2);
            #pragma unroll
            for (int mi = 0; mi < 4; mi++) ldsm4(af + mi*4, aB + MATSZ + mi*MIOFF + kof);
            #pragma unroll
            for (int mi = 0; mi < 4; mi++)
                #pragma unroll
                for (int ni = 0; ni < 4; ni++)
                    mma16816(acc[mi][ni], af + mi*4, bhf + ni*2);
        }
        __syncthreads();
    }

    // epilogue
    #pragma unroll
    for (int mi = 0; mi < 4; mi++) {
        int gm0 = m0 + wm*64 + mi*16 + g;
        #pragma unroll
        for (int ni = 0; ni < 4; ni++) {
            int gn = n0 + wn*32 + ni*8 + t*2;
            float bx = (gn     < Nreal) ? bias[gn]     : 0.f;
            float by = (gn + 1 < Nreal) ? bias[gn + 1] : 0.f;
            float c0 = acc[mi][ni][0] + bx, c1 = acc[mi][ni][1] + by;
            float c2 = acc[mi][ni][2] + bx, c3 = acc[mi][ni][3] + by;
            if (relu) {
                c0 = fmaxf(c0, 0.f); c1 = fmaxf(c1, 0.f);
                c2 = fmaxf(c2, 0.f); c3 = fmaxf(c3, 0.f);
            }
            if (gm0 < Mreal)
                *reinterpret_cast<float2*>(C + (size_t)gm0*ldc + gn) = make_float2(c0, c1);
            if (gm0 + 8 < Mreal)
                *reinterpret_cast<float2*>(C + (size_t)(gm0+8)*ldc + gn) = make_float2(c2, c3);
        }
    }
}

// ---------------- attention: 4-way q split per (b,h) ----------------
#define KSTR 65
__global__ void attn_kernel(const float* __restrict__ qkv,
                            const int* __restrict__ tmask,
                            float* __restrict__ o)
{
    int bh = blockIdx.x >> 2, z = blockIdx.x & 3;
    int b = bh / NH, h = bh % NH;
    extern __shared__ float sm[];
    float* ks = sm;
    float* vs = ks + SEQ*KSTR;
    float* qs = vs + SEQ*KSTR;
    float* sc = qs + 8*64;
    unsigned char* valid = (unsigned char*)(sc + 8*224);

    int tid = threadIdx.x, lane = tid & 31, w = tid >> 5;
    const float* base = qkv + (size_t)b * SEQ * QKVW;

    for (int i = tid; i < SEQ*HD; i += 256) {
        int t = i >> 6, e = i & 63;
        ks[t*KSTR + e] = base[(size_t)t*QKVW +   DIM + h*64 + e];
        vs[t*KSTR + e] = base[(size_t)t*QKVW + 2*DIM + h*64 + e];
    }
    for (int t = tid; t < SEQ; t += 256)
        valid[t] = (t < SEQ - TXT) ? 1 : (tmask[b*TXT + t - (SEQ-TXT)] != 0);
    __syncthreads();

    float* myq  = qs + w*64;
    float* mysc = sc + w*224;
    for (int s = (w << 2) + z; s < SEQ; s += 32) {
        myq[lane]      = base[(size_t)s*QKVW + h*64 + lane];
        myq[lane + 32] = base[(size_t)s*QKVW + h*64 + lane + 32];
        __syncwarp();

        float lmax = -INFINITY;
        for (int t = lane; t <= s; t += 32) {
            float d = -INFINITY;
            if (valid[t]) {
                d = 0.f;
                #pragma unroll
                for (int e = 0; e < 64; e++) d += myq[e] * ks[t*KSTR + e];
                d *= 0.125f;
            }
            mysc[t] = d;
            lmax = fmaxf(lmax, d);
        }
        #pragma unroll
        for (int off = 16; off; off >>= 1)
            lmax = fmaxf(lmax, __shfl_xor_sync(0xffffffffu, lmax, off));

        float lsum = 0.f;
        for (int t = lane; t <= s; t += 32) {
            float p = expf(mysc[t] - lmax);
            mysc[t] = p;
            lsum += p;
        }
        #pragma unroll
        for (int off = 16; off; off >>= 1)
            lsum += __shfl_xor_sync(0xffffffffu, lsum, off);
        float inv = 1.f / lsum;
        __syncwarp();

        float acc0 = 0.f, acc1 = 0.f;
        for (int t = 0; t <= s; t++) {
            float p = mysc[t];
            acc0 += p * vs[t*KSTR + lane];
            acc1 += p * vs[t*KSTR + lane + 32];
        }
        float* orow = o + (size_t)(b*SEQ + s)*DIM + h*64;
        orow[lane]      = acc0 * inv;
        orow[lane + 32] = acc1 * inv;
        __syncwarp();
    }
}

// ---------------- residual add + LayerNorm ----------------
__global__ void add_ln_kernel(const float* __restrict__ x, const float* __restrict__ r,
                              const float* __restrict__ sc, const float* __restrict__ bi,
                              float* __restrict__ out)
{
    __shared__ float buf[DIM];
    __shared__ float red1[8], red2[8];
    int row = blockIdx.x, tid = threadIdx.x, lane = tid & 31, w = tid >> 5;
    const float* xr = x + (size_t)row*DIM;
    const float* rr = r + (size_t)row*DIM;

    float s = 0.f;
    for (int i = tid; i < DIM; i += 256) { float v = xr[i] + rr[i]; buf[i] = v; s += v; }
    #pragma unroll
    for (int off = 16; off; off >>= 1) s += __shfl_xor_sync(0xffffffffu, s, off);
    if (lane == 0) red1[w] = s;
    __syncthreads();
    float tot = 0.f;
    #pragma unroll
    for (int i = 0; i < 8; i++) tot += red1[i];
    float mu = tot * (1.f / DIM);

    float vsum = 0.f;
    for (int i = tid; i < DIM; i += 256) { float d = buf[i] - mu; vsum += d*d; }
    #pragma unroll
    for (int off = 16; off; off >>= 1) vsum += __shfl_xor_sync(0xffffffffu, vsum, off);
    if (lane == 0) red2[w] = vsum;
    __syncthreads();
    float vtot = 0.f;
    #pragma unroll
    for (int i = 0; i < 8; i++) vtot += red2[i];
    float inv = rsqrtf(vtot * (1.f / DIM) + 1e-5f);

    float* orow = out + (size_t)row*DIM;
    for (int i = tid; i < DIM; i += 256)
        orow[i] = (buf[i] - mu) * inv * sc[i] + bi[i];
}

// ---------------- softmax: padded logits -> d_out ----------------
__global__ void softmax_rows(const float* __restrict__ in, float* __restrict__ out)
{
    int row = blockIdx.x, tid = threadIdx.x, lane = tid & 31, w = tid >> 5;
    const float* p = in + (size_t)row * NPADV;
    float* q = out + (size_t)row * VOC;
    __shared__ float smm[8], sss[8];

    float m = -INFINITY, s = 0.f;
    for (int i = tid; i < VOC; i += 256) {
        float xv = p[i];
        if (xv > m) { s = s * expf(m - xv) + 1.f; m = xv; }
        else        { s += expf(xv - m); }
    }
    #pragma unroll
    for (int off = 16; off; off >>= 1) {
        float m2 = __shfl_xor_sync(0xffffffffu, m, off);
        float s2 = __shfl_xor_sync(0xffffffffu, s, off);
        float mn = fmaxf(m, m2);
        s = s * expf(m - mn) + s2 * expf(m2 - mn);
        m = mn;
    }
    if (lane == 0) { smm[w] = m; sss[w] = s; }
    __syncthreads();
    if (tid == 0) {
        float M = smm[0], Sv = sss[0];
        #pragma unroll
        for (int i = 1; i < 8; i++) {
            float m2 = smm[i], s2 = sss[i];
            float mn = fmaxf(M, m2);
            Sv = Sv * expf(M - mn) + s2 * expf(m2 - mn);
            M = mn;
        }
        smm[0] = M; sss[0] = 1.f / Sv;
    }
    __syncthreads();
    float M = smm[0], inv = sss[0];
    for (int i = tid; i < VOC; i += 256)
        q[i] = expf(p[i] - M) * inv;
}

// ---------------- host driver ----------------
extern "C" void kernel_launch(void* const* d_in, const int* in_sizes, int n_in,
                              void* d_out, int out_size)
{
    const float* img   = (const float*)d_in[0];
    const int*   tok   = (const int*)  d_in[1];
    const int*   tmask = (const int*)  d_in[2];
    const float* temb  = (const float*)d_in[3];
    const float* sep   = (const float*)d_in[4];
    const float* Wq    = (const float*)d_in[5];
    const float* bq    = (const float*)d_in[6];
    const float* Wk    = (const float*)d_in[7];
    const float* bk    = (const float*)d_in[8];
    const float* Wv    = (const float*)d_in[9];
    const float* bv    = (const float*)d_in[10];
    const float* ln1s  = (const float*)d_in[11];
    const float* ln1b  = (const float*)d_in[12];
    const float* W1    = (const float*)d_in[13];
    const float* b1    = (const float*)d_in[14];
    const float* W2    = (const float*)d_in[15];
    const float* b2    = (const float*)d_in[16];
    const float* ln2s  = (const float*)d_in[17];
    const float* ln2b  = (const float*)d_in[18];
    const float* Wout  = (const float*)d_in[19];
    const float* bout  = (const float*)d_in[20];
    float* out = (float*)d_out;

    float *px, *pqkv, *po, *pff, *pt, *pb, *plog;
    __nv_bfloat16 *pah, *pal, *pbh, *pbl;
    cudaGetSymbolAddress((void**)&px,   g_x);
    cudaGetSymbolAddress((void**)&pqkv, g_qkv);
    cudaGetSymbolAddress((void**)&po,   g_o);
    cudaGetSymbolAddress((void**)&pff,  g_ff);
    cudaGetSymbolAddress((void**)&pt,   g_t);
    cudaGetSymbolAddress((void**)&pb,   g_b);
    cudaGetSymbolAddress((void**)&plog, g_logits);
    cudaGetSymbolAddress((void**)&pah,  g_ah);
    cudaGetSymbolAddress((void**)&pal,  g_al);
    cudaGetSymbolAddress((void**)&pbh,  g_bth);
    cudaGetSymbolAddress((void**)&pbl,  g_btl);

    const int ATTN_SMEM = (SEQ*KSTR*2 + 8*64 + 8*224) * 4 + 256;
    cudaFuncSetAttribute(attn_kernel, cudaFuncAttributeMaxDynamicSharedMemorySize, ATTN_SMEM);
    cudaFuncSetAttribute(gemm_mma, cudaFuncAttributeMaxDynamicSharedMemorySize, DSMEM);

    embed_kernel<<<MROWS, 256>>>(img, tok, temb, sep, px);

    #define ACONV(src, K)  a_convert<<<(int)(((size_t)MPAD*(K) + 255)/256), 256>>>(src, MROWS, K)
    #define GEMM(bias, C, K, ldc, Nreal, Npad, relu) \
        gemm_mma<<<dim3(MPAD/128, (Npad)/128), 256, DSMEM>>>(pah, pal, pbh, pbl, bias, C, K, ldc, Nreal, MROWS, relu)

    for (int l = 0; l < NL; l++) {
        const size_t woff = (size_t)l * NH * DIM * HD;
        // QKV
        qkvw_convert<<<(QKVW*DIM + 255)/256, 256>>>(Wq + woff, Wk + woff, Wv + woff,
                                                    bq + (size_t)l*DIM, bk + (size_t)l*DIM,
                                                    bv + (size_t)l*DIM);
        ACONV(px, DIM);
        GEMM(pb, pqkv, DIM, QKVW, QKVW, QKVW, 0);
        attn_kernel<<<BATCH*NH*4, 256, ATTN_SMEM>>>(pqkv, tmask, po);
        add_ln_kernel<<<MROWS, 256>>>(px, po, ln1s + (size_t)l*DIM, ln1b + (size_t)l*DIM, px);
        // FFN1
        ACONV(px, DIM);
        wt_convert<<<dim3(FF/32, DIM/32), dim3(32, 8)>>>(W1 + (size_t)l*DIM*FF, DIM, FF);
        GEMM(b1 + (size_t)l*FF, pff, DIM, FF, FF, FF, 1);
        // FFN2
        ACONV(pff, FF);
        wt_convert<<<dim3(DIM/32, FF/32), dim3(32, 8)>>>(W2 + (size_t)l*FF*DIM, FF, DIM);
        GEMM(b2 + (size_t)l*DIM, pt, FF, DIM, DIM, DIM, 0);
        add_ln_kernel<<<MROWS, 256>>>(px, pt, ln2s + (size_t)l*DIM, ln2b + (size_t)l*DIM, px);
    }

    // vocab projection (padded logits) + softmax into d_out
    ACONV(px, DIM);
    wt_convert<<<dim3(NPADV/32, DIM/32), dim3(32, 8)>>>(Wout, DIM, VOC);
    GEMM(bout, plog, DIM, NPADV, VOC, NPADV, 0);
    softmax_rows<<<MROWS, 256>>>(plog, out);
}